// round 1
// baseline (speedup 1.0000x reference)
#include <cuda_runtime.h>
#include <cstdint>

#define N_PTS  65536
#define M_G    1024
#define KSEL   10
#define FREEZE 256
#define CAP    192
#define TPB    128

// Per-gaussian expanded quadratic coefficients:
// q(x) = A*x0^2 + B*x0*x1 + C*x1^2 + D*x0 + E*x1 + F   (== -0.5*log2(e) * d^T Sigma^-1 d)
__device__ float4 g_p1[M_G];                         // A, B, C, D
__device__ float2 g_p2[M_G];                         // E, F
// Candidate log: slot-major so same-slot stores coalesce across the warp.
__device__ unsigned long long g_cand[(size_t)CAP * N_PTS];

__global__ void prep_kernel(const float* __restrict__ mus,
                            const float* __restrict__ covs) {
    int m = blockIdx.x * blockDim.x + threadIdx.x;
    if (m >= M_G) return;
    float mu0 = mus[2 * m], mu1 = mus[2 * m + 1];
    float a = covs[4 * m + 0];
    float b = covs[4 * m + 1];   // symmetric (A@A^T is bitwise symmetric)
    float c = covs[4 * m + 3];
    float det = a * c - b * b;
    const float L2E = 1.4426950408889634f;
    float s = -0.5f * L2E / det;
    float p00 = s * c;
    float p01 = -s * b;          // = +0.5*L2E*b/det
    float p11 = s * a;
    float A  = p00;
    float B  = 2.0f * p01;
    float C  = p11;
    float D  = -2.0f * (p00 * mu0 + p01 * mu1);
    float E  = -2.0f * (p01 * mu0 + p11 * mu1);
    float F  = -0.5f * (D * mu0 + E * mu1);
    g_p1[m] = make_float4(A, B, C, D);
    g_p2[m] = make_float2(E, F);
}

__device__ __forceinline__ float ex2_approx(float x) {
    float r;
    asm("ex2.approx.ftz.f32 %0, %1;" : "=f"(r) : "f"(x));
    return r;
}

__global__ void __launch_bounds__(TPB) render_kernel(
    const float2* __restrict__ x,
    const float*  __restrict__ cols,
    float*        __restrict__ out)
{
    __shared__ float4 sp1[M_G];
    __shared__ float2 sp2[M_G];
    int tid = threadIdx.x;
    #pragma unroll 4
    for (int i = tid; i < M_G; i += TPB) { sp1[i] = g_p1[i]; sp2[i] = g_p2[i]; }
    __syncthreads();

    int gid = blockIdx.x * TPB + tid;
    float2 xv = x[gid];
    float x0 = xv.x, x1 = xv.y;
    float xx = x0 * x0, xy = x0 * x1, yy = x1 * x1;

    float top[KSEL];
    #pragma unroll
    for (int j = 0; j < KSEL; ++j) top[j] = -3.402823466e38f;
    int cnt = 0;

    // ---- Phase A: exact running top-10 threshold over first FREEZE gaussians,
    //      log every guard-passing (q, m) ----
    #pragma unroll 1
    for (int m = 0; m < FREEZE; ++m) {
        float4 c1 = sp1[m];
        float2 c2 = sp2[m];
        float q = fmaf(c1.x, xx,
                  fmaf(c1.y, xy,
                  fmaf(c1.z, yy,
                  fmaf(c1.w, x0,
                  fmaf(c2.x, x1, c2.y)))));
        if (q >= top[KSEL - 1]) {
            if (cnt < CAP)
                g_cand[(size_t)cnt * N_PTS + gid] =
                    ((unsigned long long)__float_as_uint(q) << 32) | (unsigned)m;
            cnt++;
            #pragma unroll
            for (int j = KSEL - 1; j >= 1; --j)
                top[j] = fmaxf(fminf(q, top[j - 1]), top[j]);
            top[0] = fmaxf(top[0], q);
        }
    }
    float tau = top[KSEL - 1];   // frozen threshold: 10th-of-subset <= final 10th

    // ---- Phase B: branch-light record-only scan ----
    #pragma unroll 4
    for (int m = FREEZE; m < M_G; ++m) {
        float4 c1 = sp1[m];
        float2 c2 = sp2[m];
        float q = fmaf(c1.x, xx,
                  fmaf(c1.y, xy,
                  fmaf(c1.z, yy,
                  fmaf(c1.w, x0,
                  fmaf(c2.x, x1, c2.y)))));
        if (q >= tau && cnt < CAP) {
            g_cand[(size_t)cnt * N_PTS + gid] =
                ((unsigned long long)__float_as_uint(q) << 32) | (unsigned)m;
            cnt++;
        }
    }

    // ---- Post 1: exact 10th-largest q over the candidate set ----
    int mc = __reduce_max_sync(0xFFFFFFFFu, cnt);
    #pragma unroll
    for (int j = 0; j < KSEL; ++j) top[j] = -3.402823466e38f;
    #pragma unroll 1
    for (int i = 0; i < mc; ++i) {
        float q = -3.402823466e38f;
        if (i < cnt) {
            unsigned long long cd = g_cand[(size_t)i * N_PTS + gid];
            q = __uint_as_float((unsigned)(cd >> 32));
        }
        if (q >= top[KSEL - 1]) {
            #pragma unroll
            for (int j = KSEL - 1; j >= 1; --j)
                top[j] = fmaxf(fminf(q, top[j - 1]), top[j]);
            top[0] = fmaxf(top[0], q);
        }
    }
    float t = top[KSEL - 1];

    // ---- Post 2: accumulate exp2(q) * color for q >= t ----
    float r0 = 0.f, r1 = 0.f, r2 = 0.f, den = 0.f;
    int c = 0;
    #pragma unroll 1
    for (int i = 0; i < mc; ++i) {
        if (i < cnt) {
            unsigned long long cd = g_cand[(size_t)i * N_PTS + gid];
            float q = __uint_as_float((unsigned)(cd >> 32));
            if (q >= t) {
                int m = (int)(unsigned)(cd & 0xFFFFFFFFu);
                float v = ex2_approx(q);
                r0 = fmaf(v, __ldg(&cols[3 * m + 0]), r0);
                r1 = fmaf(v, __ldg(&cols[3 * m + 1]), r1);
                r2 = fmaf(v, __ldg(&cols[3 * m + 2]), r2);
                den += v;
                c++;
            }
        }
    }

    // Tie trim: if more than K entries equal the threshold, drop the
    // highest-index ones (matches jax top_k lowest-index tie-break).
    if (__any_sync(0xFFFFFFFFu, c > KSEL)) {
        int excess = c - KSEL;
        #pragma unroll 1
        for (int i = mc - 1; i >= 0; --i) {
            if (excess > 0 && i < cnt) {
                unsigned long long cd = g_cand[(size_t)i * N_PTS + gid];
                float q = __uint_as_float((unsigned)(cd >> 32));
                if (q == t) {
                    int m = (int)(unsigned)(cd & 0xFFFFFFFFu);
                    float v = ex2_approx(q);
                    r0 = fmaf(-v, __ldg(&cols[3 * m + 0]), r0);
                    r1 = fmaf(-v, __ldg(&cols[3 * m + 1]), r1);
                    r2 = fmaf(-v, __ldg(&cols[3 * m + 2]), r2);
                    den -= v;
                    excess--;
                }
            }
        }
    }

    float inv = 1.0f / (den + 1e-6f);
    out[3 * gid + 0] = r0 * inv;
    out[3 * gid + 1] = r1 * inv;
    out[3 * gid + 2] = r2 * inv;
}

extern "C" void kernel_launch(void* const* d_in, const int* in_sizes, int n_in,
                              void* d_out, int out_size) {
    const float*  xx   = (const float*)d_in[0];   // [N, 2]
    const float*  mus  = (const float*)d_in[1];   // [1, M, 2]
    const float*  covs = (const float*)d_in[2];   // [1, M, 2, 2]
    const float*  cols = (const float*)d_in[3];   // [1, M, 3]
    float* out = (float*)d_out;                   // [N, 3]

    prep_kernel<<<(M_G + 127) / 128, 128>>>(mus, covs);
    render_kernel<<<N_PTS / TPB, TPB>>>((const float2*)xx, cols, out);
}